// round 16
// baseline (speedup 1.0000x reference)
#include <cuda_runtime.h>
#include <cuda_fp16.h>
#include <cstdint>

#define NB    4
#define NS    1024
#define NHID  1024
#define NHEAD 16
#define NHD   64
#define NTAB  127
#define NTABP 128
#define BHS   (NB*NHEAD*NS)   // 65536
#define NM    (NB*NS)         // 4096

typedef __half h16;

// ---------------- scratch (device globals; no allocations allowed) ----------------
__device__ h16  g_x  [(size_t)3*NM*NHID];             // fp16 inputs (q,k,v)
__device__ h16  g_wt [(size_t)3*NHEAD*NHD*NHID];      // W^T per head fp16
__device__ h16  g_wfc[(size_t)NHID*NHID];             // Wfc fp16 ([o][k])
__device__ h16  g_q  [(size_t)BHS*NHD];               // q/8  [bn][s][d]  (pre-scaled)
__device__ h16  g_k  [(size_t)BHS*NHD];               // k  [bn][s][d]
__device__ h16  g_vt [(size_t)BHS*NHD];               // v^T [bn][d][s]
__device__ h16  g_rpvt[NHD*NTABP];                    // rp_v^T (col 127 = 0)
__device__ h16  g_rpkp[NTABP*NHD];                    // rp_k padded [t][d]
__device__ h16  g_ao [(size_t)NM*NHID];               // attn out [b*s][hid]

// =============================== helpers =====================================
__device__ __forceinline__ uint32_t s2u(const void* p) {
    uint32_t a;
    asm("{ .reg .u64 t; cvta.to.shared.u64 t, %1; cvt.u32.u64 %0, t; }" : "=r"(a) : "l"(p));
    return a;
}
__device__ __forceinline__ void cpa16(uint32_t d, const void* s) {
    asm volatile("cp.async.cg.shared.global [%0], [%1], 16;" :: "r"(d), "l"(s));
}
__device__ __forceinline__ void cp_commit() { asm volatile("cp.async.commit_group;"); }
template<int N> __device__ __forceinline__ void cp_wait() {
    asm volatile("cp.async.wait_group %0;" :: "n"(N));
}
__device__ __forceinline__ void mma16(float* c, const uint32_t* a, const uint32_t* b) {
    asm volatile(
        "mma.sync.aligned.m16n8k16.row.col.f32.f16.f16.f32 "
        "{%0,%1,%2,%3}, {%4,%5,%6,%7}, {%8,%9}, {%0,%1,%2,%3};"
        : "+f"(c[0]), "+f"(c[1]), "+f"(c[2]), "+f"(c[3])
        : "r"(a[0]), "r"(a[1]), "r"(a[2]), "r"(a[3]), "r"(b[0]), "r"(b[1]));
}
__device__ __forceinline__ void ldm4(uint32_t* d, uint32_t saddr) {
    asm volatile("ldmatrix.sync.aligned.m8n8.x4.shared.b16 {%0,%1,%2,%3}, [%4];"
                 : "=r"(d[0]), "=r"(d[1]), "=r"(d[2]), "=r"(d[3]) : "r"(saddr));
}
__device__ __forceinline__ uint32_t ldh2(const h16* p) { return *(const uint32_t*)p; }
__device__ __forceinline__ uint32_t pk2(float x, float y) {
    __half2 h = __floats2half2_rn(x, y);
    return *(uint32_t*)&h;
}

#define TS 72
#define T_BUF (128*TS)
#define SMEM_GEMM (4*T_BUF*2)   // 73728 B (2-stage A+B)

// 128x64-half tile, 128 threads
__device__ __forceinline__ void load_t(uint32_t ts, const h16* __restrict__ G, int ld, int tid) {
    #pragma unroll
    for (int i = 0; i < 8; i++) {
        int idx = tid + i*128;
        int m = idx >> 3, ch = idx & 7;
        cpa16(ts + (uint32_t)(m*TS + ch*8)*2, G + (size_t)m*ld + ch*8);
    }
}

// warp tile 64x64 via ldmatrix: 4 m-frags x 8 n-groups
__device__ __forceinline__ void mma_tile64(uint32_t As_u, uint32_t Bs_u,
                                           float acc[4][8][4], int wm, int wn, int lane) {
    const int mat   = lane >> 3;
    const int arow  = (lane & 7) + 8*(mat & 1);
    const int akoff = 8*(mat >> 1);
    const int bg    = (mat >> 1);
    const int bkoff = 8*(mat & 1);
    const int brow  = lane & 7;
    #pragma unroll
    for (int ks = 0; ks < 4; ks++) {
        const int k0 = ks*16;
        uint32_t a[4][4], b[4][4];
        #pragma unroll
        for (int f = 0; f < 4; f++) {
            const int bm = wm*64 + f*16;
            ldm4(a[f], As_u + (uint32_t)((bm + arow)*TS + k0 + akoff)*2);
        }
        #pragma unroll
        for (int gp = 0; gp < 4; gp++) {
            const int bn = wn*64 + (gp*2 + bg)*8;
            ldm4(b[gp], Bs_u + (uint32_t)((bn + brow)*TS + k0 + bkoff)*2);
        }
        #pragma unroll
        for (int f = 0; f < 4; f++)
            #pragma unroll
            for (int g = 0; g < 8; g++) mma16(acc[f][g], a[f], &b[g>>1][(g&1)*2]);
    }
}

// =============================================================================
__global__ __launch_bounds__(256) void cvt3_kernel(const float* __restrict__ q,
                                                   const float* __restrict__ k,
                                                   const float* __restrict__ v)
{
    int i = blockIdx.x * 256 + threadIdx.x;
    int mode = blockIdx.y;
    const float* in = (mode == 0) ? q : ((mode == 1) ? k : v);
    h16* dst = g_x + (size_t)mode*NM*NHID;
    float4 val = ((const float4*)in)[i];
    __half2 h0 = __floats2half2_rn(val.x, val.y);
    __half2 h1 = __floats2half2_rn(val.z, val.w);
    uint2 u; u.x = *(uint32_t*)&h0; u.y = *(uint32_t*)&h1;
    ((uint2*)dst)[i] = u;
}

__global__ __launch_bounds__(256) void cvtw_kernel(const float* __restrict__ in)
{
    int i = blockIdx.x * 256 + threadIdx.x;
    float4 v = ((const float4*)in)[i];
    __half2 h0 = __floats2half2_rn(v.x, v.y);
    __half2 h1 = __floats2half2_rn(v.z, v.w);
    uint2 u; u.x = *(uint32_t*)&h0; u.y = *(uint32_t*)&h1;
    ((uint2*)g_wfc)[i] = u;
}

__global__ __launch_bounds__(256) void prep_kernel(const float* __restrict__ wq,
                                                   const float* __restrict__ wk,
                                                   const float* __restrict__ wv,
                                                   const float* __restrict__ rpv,
                                                   const float* __restrict__ rpk)
{
    __shared__ float tile[64*65];
    const int hb = blockIdx.x, n = blockIdx.y, op = blockIdx.z;
    const float* W = (op==0 ? wq : (op==1 ? wk : wv)) + ((size_t)n*NHID + hb*64)*NHD;
    for (int e = threadIdx.x; e < 64*64; e += 256) {
        int h = e >> 6, d = e & 63;
        tile[h*65 + d] = W[(size_t)h*NHD + d];
    }
    __syncthreads();
    size_t ob = ((size_t)(op*NHEAD + n)*NHD)*NHID + hb*64;
    for (int e = threadIdx.x; e < 64*64; e += 256) {
        int d = e >> 6, h = e & 63;
        g_wt[ob + (size_t)d*NHID + h] = __float2half(tile[h*65 + d]);
    }
    if (op == 0 && n == 0 && hb == 0) {
        for (int e = threadIdx.x; e < NHD*NTABP; e += 256) {
            int d = e >> 7, t = e & 127;
            float v = (t < NTAB) ? rpv[(size_t)t*NHD + d] : 0.f;
            g_rpvt[(size_t)d*NTABP + t] = __float2half(v);
        }
    }
    if (op == 0 && n == 0 && hb == 1) {
        for (int e = threadIdx.x; e < NTABP*NHD; e += 256) {
            int t = e >> 6, d = e & 63;
            float v = (t < NTAB) ? rpk[(size_t)t*NHD + d] : 0.f;
            g_rpkp[e] = __float2half(v);
        }
    }
}

// =============================================================================
// K1: QKV projection, 128x128 tiles, 4 warps x 64x64.  grid (32, 8, 3), 128 thr.
// q output is pre-scaled by 0.125.
// =============================================================================
__global__ __launch_bounds__(128) void proj_mma(const float* __restrict__ bq_,
                                                const float* __restrict__ bk_,
                                                const float* __restrict__ bv_)
{
    extern __shared__ char smc[];
    const uint32_t As_u = s2u(smc);
    const uint32_t Bs_u = As_u + 2*T_BUF*2;
    const int tid = threadIdx.x, lane = tid & 31, wid = tid >> 5;
    const int wm = wid & 1, wn = wid >> 1;
    const int m0 = blockIdx.x * 128, ny = blockIdx.y, op = blockIdx.z;

    const h16* A0 = g_x + (size_t)op*NM*NHID + (size_t)m0*NHID;
    const h16* B0 = g_wt + (size_t)(op*NHEAD + ny*2)*NHD*NHID;

    float acc[4][8][4];
    #pragma unroll
    for (int f = 0; f < 4; f++)
        #pragma unroll
        for (int g = 0; g < 8; g++)
            #pragma unroll
            for (int e = 0; e < 4; e++) acc[f][g][e] = 0.f;

    load_t(As_u, A0, NHID, tid);
    load_t(Bs_u, B0, NHID, tid);
    cp_commit();
    for (int kt = 0; kt < 16; kt++) {
        if (kt + 1 < 16) {
            int nb = (kt+1) & 1;
            load_t(As_u + nb*T_BUF*2, A0 + (kt+1)*64, NHID, tid);
            load_t(Bs_u + nb*T_BUF*2, B0 + (kt+1)*64, NHID, tid);
            cp_commit();
            cp_wait<1>();
        } else cp_wait<0>();
        __syncthreads();
        mma_tile64(As_u + (kt&1)*T_BUF*2, Bs_u + (kt&1)*T_BUF*2, acc, wm, wn, lane);
        __syncthreads();
    }

    const int b = m0 >> 10, s0 = m0 & 1023;
    const int r = lane >> 2, cq = lane & 3;
    const float* bias = (op == 0) ? bq_ : ((op == 1) ? bk_ : bv_);

    if (op < 2) {
        h16* outb = op ? g_k : g_q;
        const float sc = (op == 0) ? 0.125f : 1.f;
        #pragma unroll
        for (int f = 0; f < 4; f++) {
            int ml = wm*64 + f*16 + r;
            #pragma unroll
            for (int g = 0; g < 8; g++) {
                int dp = wn*64 + g*8 + 2*cq;
                int nh = ny*2 + (dp >> 6), d = dp & 63;
                float b0 = bias[nh*NHD + d], b1 = bias[nh*NHD + d + 1];
                h16* out = outb + ((size_t)(b*NHEAD + nh)*NS + s0)*NHD;
                *(__half2*)&out[(size_t)ml*NHD + d] =
                    __floats2half2_rn((acc[f][g][0]+b0)*sc, (acc[f][g][1]+b1)*sc);
                *(__half2*)&out[(size_t)(ml+8)*NHD + d] =
                    __floats2half2_rn((acc[f][g][2]+b0)*sc, (acc[f][g][3]+b1)*sc);
            }
        }
    } else {
        h16* stage = (h16*)smc;                   // [128 dp][136]
        #pragma unroll
        for (int f = 0; f < 4; f++) {
            int ml = wm*64 + f*16 + r;
            #pragma unroll
            for (int g = 0; g < 8; g++) {
                int dp = wn*64 + g*8 + 2*cq;
                int nh = ny*2 + (dp >> 6), d = dp & 63;
                float b0 = bias[nh*NHD + d], b1 = bias[nh*NHD + d + 1];
                stage[(dp  )*136 + ml    ] = __float2half(acc[f][g][0] + b0);
                stage[(dp+1)*136 + ml    ] = __float2half(acc[f][g][1] + b1);
                stage[(dp  )*136 + ml + 8] = __float2half(acc[f][g][2] + b0);
                stage[(dp+1)*136 + ml + 8] = __float2half(acc[f][g][3] + b1);
            }
        }
        __syncthreads();
        const int dp = tid;                        // 128 threads -> one dp row each
        const int nh = ny*2 + (dp >> 6), d = dp & 63;
        h16* dst = g_vt + ((size_t)(b*NHEAD + nh)*NHD + d)*NS + s0;
        const uint4* src = (const uint4*)(stage + dp*136);
        #pragma unroll
        for (int j = 0; j < 16; j++) ((uint4*)dst)[j] = src[j];
    }
}

// =============================================================================
// K3: fused flash attention (R15 config, unchanged).
// smem: ks[64][72]h @0 | vs @9216 | band @18432 | qbh/wbh @34816 = 52224
// =============================================================================
#define ATTN_SMEM 52224

__global__ __launch_bounds__(128, 4) void attn_fused()
{
    extern __shared__ char smc[];
    h16*  ks   = (h16*)(smc);
    h16*  vs   = (h16*)(smc + 9216);
    h16*  band = (h16*)(smc + 18432);
    h16*  qbh  = (h16*)(smc + 34816);

    const int tid = threadIdx.x, lane = tid & 31, w = tid >> 5;
    const int i0 = blockIdx.x * 64, bn = blockIdx.y;
    const int r = lane >> 2, cq = lane & 3;
    const int cq2 = cq*2;
    const int wb16 = w*16;
    const int lr0 = wb16 + r;
    const int ia0 = i0 + lr0;

    const int mat   = lane >> 3;
    const int arow  = (lane & 7) + 8*(mat & 1);
    const int akoff = 8*(mat >> 1);
    const int bg    = (mat >> 1);
    const int bkoff = 8*(mat & 1);
    const int brow  = lane & 7;

    const uint32_t ks_u = s2u(ks), vs_u = s2u(vs), bd_u = s2u(band);

    const h16* qg = g_q + ((size_t)bn*NS + i0)*NHD;
    for (int e = tid; e < 64*8; e += 128) {
        int row = e >> 3, ch = e & 7;
        cpa16(bd_u + (uint32_t)(row*72 + ch*8)*2, qg + (size_t)row*NHD + ch*8);
    }
    for (int e = tid; e < 128*8; e += 128) {
        int row = e >> 3, ch = e & 7;
        cpa16(ks_u + (uint32_t)(row*72 + ch*8)*2, g_rpkp + (size_t)row*NHD + ch*8);
    }
    cp_commit();
    cp_wait<0>();
    __syncthreads();

    uint32_t qf[4][4];
    #pragma unroll
    for (int kk = 0; kk < 4; kk++)
        ldm4(qf[kk], bd_u + (uint32_t)((wb16 + arow)*72 + kk*16 + akoff)*2);

    {
        float qacc[16][4];
        #pragma unroll
        for (int g = 0; g < 16; g++)
            #pragma unroll
            for (int e = 0; e < 4; e++) qacc[g][e] = 0.f;
        #pragma unroll
        for (int kk = 0; kk < 4; kk++) {
            const int k0 = kk*16;
            #pragma unroll
            for (int gp = 0; gp < 8; gp++) {
                uint32_t b[4];
                ldm4(b, ks_u + (uint32_t)(((gp*2 + bg)*8 + brow)*72 + k0 + bkoff)*2);
                mma16(qacc[gp*2    ], qf[kk], &b[0]);
                mma16(qacc[gp*2 + 1], qf[kk], &b[2]);
            }
        }
        __syncthreads();
        #pragma unroll
        for (int g = 0; g < 16; g++) {
            const int t = g*8 + cq2;
            *(uint32_t*)&qbh[lr0*136 + t]     = pk2(qacc[g][0], qacc[g][1]);
            *(uint32_t*)&qbh[(lr0+8)*136 + t] = pk2(qacc[g][2], qacc[g][3]);
        }
    }
    for (int e = tid; e < 64*128/8; e += 128)
        ((uint4*)band)[e] = make_uint4(0,0,0,0);
    __syncthreads();

    const float el0 = __expf(__half2float(qbh[lr0*136 +   0]));
    const float er0 = __expf(__half2float(qbh[lr0*136 + 126]));
    const float el1 = __expf(__half2float(qbh[(lr0+8)*136 +   0]));
    const float er1 = __expf(__half2float(qbh[(lr0+8)*136 + 126]));

    const h16* kg = g_k + (size_t)bn*NS*NHD;
    const h16* vg = g_vt + (size_t)bn*NHD*NS;

    auto ldKV = [&](int jt) {
        for (int e = tid; e < 64*8; e += 128) {
            int row = e >> 3, ch = e & 7;
            cpa16(ks_u + (uint32_t)(row*72 + ch*8)*2,
                  kg + (size_t)(jt*64+row)*NHD + ch*8);
            cpa16(vs_u + (uint32_t)(row*72 + ch*8)*2,
                  vg + (size_t)row*NS + jt*64 + ch*8);
        }
    };
    ldKV(0); cp_commit();

    float o[8][4];
    #pragma unroll
    for (int g = 0; g < 8; g++)
        #pragma unroll
        for (int e = 0; e < 4; e++) o[g][e] = 0.f;
    float l0 = 0.f, l1 = 0.f;
    float rs0 = 0.f, rs1 = 0.f;

    for (int jt = 0; jt < 16; jt++) {
        cp_wait<0>();
        __syncthreads();

        float s[8][4];
        #pragma unroll
        for (int g = 0; g < 8; g++)
            #pragma unroll
            for (int e = 0; e < 4; e++) s[g][e] = 0.f;
        #pragma unroll
        for (int kk = 0; kk < 4; kk++) {
            const int k0 = kk*16;
            #pragma unroll
            for (int gp = 0; gp < 4; gp++) {
                uint32_t b[4];
                ldm4(b, ks_u + (uint32_t)(((gp*2 + bg)*8 + brow)*72 + k0 + bkoff)*2);
                mma16(s[gp*2    ], qf[kk], &b[0]);
                mma16(s[gp*2 + 1], qf[kk], &b[2]);
            }
        }

        const int d64 = jt*64 - i0;
        if (d64 <= -128) {
            #pragma unroll
            for (int g = 0; g < 8; g++) {
                float p0 = __expf(s[g][0])*el0;
                float p1 = __expf(s[g][1])*el0;
                float p2 = __expf(s[g][2])*el1;
                float p3 = __expf(s[g][3])*el1;
                l0 += p0 + p1; l1 += p2 + p3;
                s[g][0]=p0; s[g][1]=p1; s[g][2]=p2; s[g][3]=p3;
            }
        } else if (d64 >= 128) {
            #pragma unroll
            for (int g = 0; g < 8; g++) {
                float p0 = __expf(s[g][0])*er0;
                float p1 = __expf(s[g][1])*er0;
                float p2 = __expf(s[g][2])*er1;
                float p3 = __expf(s[g][3])*er1;
                l0 += p0 + p1; l1 += p2 + p3;
                rs0 += p0 + p1; rs1 += p2 + p3;
                s[g][0]=p0; s[g][1]=p1; s[g][2]=p2; s[g][3]=p3;
            }
        } else {
            #pragma unroll
            for (int g = 0; g < 8; g++) {
                const int j0 = jt*64 + g*8 + cq2;
                const int t0 = j0 - ia0 + 63;
                const int t8 = t0 - 8;
                int c0 = t0 < 0 ? 0 : (t0 > 126 ? 126 : t0);
                int c1 = t0+1 < 0 ? 0 : (t0+1 > 126 ? 126 : t0+1);
                int c2 = t8 < 0 ? 0 : (t8 > 126 ? 126 : t8);
                int c3 = t8+1 < 0 ? 0 : (t8+1 > 126 ? 126 : t8+1);
                float p0 = __expf(s[g][0] + __half2float(qbh[lr0*136 + c0]));
                float p1 = __expf(s[g][1] + __half2float(qbh[lr0*136 + c1]));
                float p2 = __expf(s[g][2] + __half2float(qbh[(lr0+8)*136 + c2]));
                float p3 = __expf(s[g][3] + __half2float(qbh[(lr0+8)*136 + c3]));
                band[lr0*128 + c0]     = __float2half(p0);
                band[lr0*128 + c1]     = __float2half(p1);
                band[(lr0+8)*128 + c2] = __float2half(p2);
                band[(lr0+8)*128 + c3] = __float2half(p3);
                l0 += p0 + p1; l1 += p2 + p3;
                if (t0   >= 126) rs0 += p0;
                if (t0+1 >= 126) rs0 += p1;
                if (t8   >= 126) rs1 += p2;
                if (t8+1 >= 126) rs1 += p3;
                s[g][0]=p0; s[g][1]=p1; s[g][2]=p2; s[g][3]=p3;
            }
        }

        #pragma unroll
        for (int kk = 0; kk < 4; kk++) {
            const int k0 = kk*16;
            uint32_t a[4];
            a[0] = pk2(s[2*kk  ][0], s[2*kk  ][1]);
            a[1] = pk2(s[2*kk  ][2], s[2*kk  ][3]);
            a[2] = pk2(s[2*kk+1][0], s[2*kk+1][1]);
            a[3] = pk2(s[2*kk+1][2], s[2*kk+1][3]);
            #pragma unroll
            for (int gp = 0; gp < 4; gp++) {
                uint32_t b[4];
                ldm4(b, vs_u + (uint32_t)(((gp*2 + bg)*8 + brow)*72 + k0 + bkoff)*2);
                mma16(o[gp*2    ], a, &b[0]);
                mma16(o[gp*2 + 1], a, &b[2]);
            }
        }
        __syncthreads();
        if (jt + 1 < 16) { ldKV(jt+1); cp_commit(); }
    }

    // ---- epilogue ----
    __syncwarp();
    float bs0 = 0.f, bs1 = 0.f;
    for (int t = 1 + cq; t <= 125; t += 4) {
        bs0 += __half2float(band[lr0*128 + t]);
        bs1 += __half2float(band[(lr0+8)*128 + t]);
    }
    #pragma unroll
    for (int off = 1; off <= 2; off <<= 1) {
        l0  += __shfl_xor_sync(0xffffffffu, l0,  off);
        l1  += __shfl_xor_sync(0xffffffffu, l1,  off);
        rs0 += __shfl_xor_sync(0xffffffffu, rs0, off);
        rs1 += __shfl_xor_sync(0xffffffffu, rs1, off);
        bs0 += __shfl_xor_sync(0xffffffffu, bs0, off);
        bs1 += __shfl_xor_sync(0xffffffffu, bs1, off);
    }
    const float ls0 = l0 - rs0 - bs0;
    const float ls1 = l1 - rs1 - bs1;
    const float inv0 = 1.f / l0, inv1 = 1.f / l1;
    #pragma unroll
    for (int g = 0; g < 8; g++) {
        o[g][0] *= inv0; o[g][1] *= inv0; o[g][2] *= inv1; o[g][3] *= inv1;
    }
    __syncthreads();

    h16* rvs = (h16*)smc;
    h16* wbh = qbh;
    for (int e = tid; e < 64*16; e += 128) {
        int d = e >> 4, ch = e & 15;
        cpa16(s2u(rvs + d*136 + ch*8), g_rpvt + (size_t)d*NTABP + ch*8);
    }
    cp_commit();
    for (int t = cq; t < 128; t += 4) {
        float v0 = 0.f, v1 = 0.f;
        if (t == 0)        { v0 = ls0*inv0; v1 = ls1*inv1; }
        else if (t == 126) { v0 = rs0*inv0; v1 = rs1*inv1; }
        else if (t < 126) {
            int j0 = ia0 + t - 63;
            int j1 = j0 + 8;
            if (j0 >= 0 && j0 < NS) v0 = __half2float(band[lr0*128 + t]) * inv0;
            if (j1 >= 0 && j1 < NS) v1 = __half2float(band[(lr0+8)*128 + t]) * inv1;
        }
        wbh[lr0*136 + t]     = __float2half(v0);
        wbh[(lr0+8)*136 + t] = __float2half(v1);
    }
    cp_wait<0>();
    __syncthreads();

    #pragma unroll
    for (int kk = 0; kk < 8; kk++) {
        const int k0 = kk*16;
        uint32_t a[4];
        a[0] = ldh2(&wbh[(lr0  )*136 + k0 + cq2    ]);
        a[1] = ldh2(&wbh[(lr0+8)*136 + k0 + cq2    ]);
        a[2] = ldh2(&wbh[(lr0  )*136 + k0 + cq2 + 8]);
        a[3] = ldh2(&wbh[(lr0+8)*136 + k0 + cq2 + 8]);
        #pragma unroll
        for (int g = 0; g < 8; g++) {
            uint32_t b[2];
            b[0] = ldh2(&rvs[(g*8+r)*136 + k0 + cq2    ]);
            b[1] = ldh2(&rvs[(g*8+r)*136 + k0 + cq2 + 8]);
            mma16(o[g], a, b);
        }
    }

    const int b = bn >> 4, n = bn & 15;
    #pragma unroll
    for (int g = 0; g < 8; g++) {
        const int d = g*8 + cq2;
        h16* p0 = g_ao + ((size_t)(b*NS + i0 + lr0))*NHID + n*NHD + d;
        h16* p1 = g_ao + ((size_t)(b*NS + i0 + lr0 + 8))*NHID + n*NHD + d;
        *(__half2*)p0 = __floats2half2_rn(o[g][0], o[g][1]);
        *(__half2*)p1 = __floats2half2_rn(o[g][2], o[g][3]);
    }
}

// =============================================================================
// K5: final FC, 128x128 tiles, 4 warps x 64x64.  grid (32, 8), 128 thr.
// =============================================================================
__global__ __launch_bounds__(128) void fc_mma(const float* __restrict__ bfc,
                                              float* __restrict__ out)
{
    extern __shared__ char smc[];
    const uint32_t As_u = s2u(smc);
    const uint32_t Bs_u = As_u + 2*T_BUF*2;
    const int tid = threadIdx.x, lane = tid & 31, wid = tid >> 5;
    const int wm = wid & 1, wn = wid >> 1;
    const int m0 = blockIdx.x * 128, o0 = blockIdx.y * 128;

    const h16* A0 = g_ao + (size_t)m0*NHID;
    const h16* B0 = g_wfc + (size_t)o0*NHID;

    float acc[4][8][4];
    #pragma unroll
    for (int f = 0; f < 4; f++)
        #pragma unroll
        for (int g = 0; g < 8; g++)
            #pragma unroll
            for (int e = 0; e < 4; e++) acc[f][g][e] = 0.f;

    load_t(As_u, A0, NHID, tid);
    load_t(Bs_u, B0, NHID, tid);
    cp_commit();
    for (int kt = 0; kt < 16; kt++) {
        if (kt + 1 < 16) {
            int nb = (kt+1) & 1;
            load_t(As_u + nb*T_BUF*2, A0 + (kt+1)*64, NHID, tid);
            load_t(Bs_u + nb*T_BUF*2, B0 + (kt+1)*64, NHID, tid);
            cp_commit();
            cp_wait<1>();
        } else cp_wait<0>();
        __syncthreads();
        mma_tile64(As_u + (kt&1)*T_BUF*2, Bs_u + (kt&1)*T_BUF*2, acc, wm, wn, lane);
        __syncthreads();
    }

    const int r = lane >> 2, cq = lane & 3;
    #pragma unroll
    for (int f = 0; f < 4; f++) {
        int m = m0 + wm*64 + f*16 + r;
        #pragma unroll
        for (int g = 0; g < 8; g++) {
            int o = o0 + wn*64 + g*8 + 2*cq;
            float b0 = bfc[o], b1 = bfc[o+1];
            *(float2*)&out[(size_t)m*NHID + o]     = make_float2(acc[f][g][0]+b0, acc[f][g][1]+b1);
            *(float2*)&out[(size_t)(m+8)*NHID + o] = make_float2(acc[f][g][2]+b0, acc[f][g][3]+b1);
        }
    }
}

// =============================================================================
extern "C" void kernel_launch(void* const* d_in, const int* in_sizes, int n_in,
                              void* d_out, int out_size)
{
    (void)in_sizes; (void)n_in; (void)out_size;
    const float* query = (const float*)d_in[0];
    const float* key   = (const float*)d_in[1];
    const float* value = (const float*)d_in[2];
    const float* Wq    = (const float*)d_in[3];
    const float* Wk    = (const float*)d_in[4];
    const float* Wv    = (const float*)d_in[5];
    const float* bq    = (const float*)d_in[6];
    const float* bk    = (const float*)d_in[7];
    const float* bv    = (const float*)d_in[8];
    const float* rpk   = (const float*)d_in[9];
    const float* rpv   = (const float*)d_in[10];
    const float* Wfc   = (const float*)d_in[11];
    const float* bfc   = (const float*)d_in[12];
    float* out = (float*)d_out;

    cudaFuncSetAttribute(proj_mma,   cudaFuncAttributeMaxDynamicSharedMemorySize, SMEM_GEMM);
    cudaFuncSetAttribute(fc_mma,     cudaFuncAttributeMaxDynamicSharedMemorySize, SMEM_GEMM);
    cudaFuncSetAttribute(attn_fused, cudaFuncAttributeMaxDynamicSharedMemorySize, ATTN_SMEM);

    cvt3_kernel<<<dim3(4096, 3), 256>>>(query, key, value);          // 1
    prep_kernel<<<dim3(16, 16, 3), 256>>>(Wq, Wk, Wv, rpv, rpk);     // 2
    proj_mma<<<dim3(32, 8, 3), 128, SMEM_GEMM>>>(bq, bk, bv);        // 3
    attn_fused<<<dim3(16, 64), 128, ATTN_SMEM>>>();                  // 4 <- profiled
    cvtw_kernel<<<1024, 256>>>(Wfc);                                 // 5
    fc_mma<<<dim3(32, 8), 128, SMEM_GEMM>>>(bfc, out);               // 6
}

// round 17
// speedup vs baseline: 1.0101x; 1.0101x over previous
#include <cuda_runtime.h>
#include <cuda_fp16.h>
#include <cstdint>

#define NB    4
#define NS    1024
#define NHID  1024
#define NHEAD 16
#define NHD   64
#define NTAB  127
#define NTABP 128
#define BHS   (NB*NHEAD*NS)   // 65536
#define NM    (NB*NS)         // 4096

typedef __half h16;

// ---------------- scratch (device globals; no allocations allowed) ----------------
__device__ h16  g_x  [(size_t)3*NM*NHID];             // fp16 inputs (q,k,v)
__device__ h16  g_wt [(size_t)3*NHEAD*NHD*NHID];      // W^T per head fp16
__device__ h16  g_wfc[(size_t)NHID*NHID];             // Wfc fp16 ([o][k])
__device__ h16  g_q  [(size_t)BHS*NHD];               // q/8  [bn][s][d]  (pre-scaled)
__device__ h16  g_k  [(size_t)BHS*NHD];               // k  [bn][s][d]
__device__ h16  g_vt [(size_t)BHS*NHD];               // v^T [bn][d][s]
__device__ h16  g_rpvt[NHD*NTABP];                    // rp_v^T (col 127 = 0)
__device__ h16  g_rpkp[NTABP*NHD];                    // rp_k padded [t][d]
__device__ h16  g_ao [(size_t)NM*NHID];               // attn out [b*s][hid]

// =============================== helpers =====================================
__device__ __forceinline__ uint32_t s2u(const void* p) {
    uint32_t a;
    asm("{ .reg .u64 t; cvta.to.shared.u64 t, %1; cvt.u32.u64 %0, t; }" : "=r"(a) : "l"(p));
    return a;
}
__device__ __forceinline__ void cpa16(uint32_t d, const void* s) {
    asm volatile("cp.async.cg.shared.global [%0], [%1], 16;" :: "r"(d), "l"(s));
}
__device__ __forceinline__ void cp_commit() { asm volatile("cp.async.commit_group;"); }
template<int N> __device__ __forceinline__ void cp_wait() {
    asm volatile("cp.async.wait_group %0;" :: "n"(N));
}
__device__ __forceinline__ void mma16(float* c, const uint32_t* a, const uint32_t* b) {
    asm volatile(
        "mma.sync.aligned.m16n8k16.row.col.f32.f16.f16.f32 "
        "{%0,%1,%2,%3}, {%4,%5,%6,%7}, {%8,%9}, {%0,%1,%2,%3};"
        : "+f"(c[0]), "+f"(c[1]), "+f"(c[2]), "+f"(c[3])
        : "r"(a[0]), "r"(a[1]), "r"(a[2]), "r"(a[3]), "r"(b[0]), "r"(b[1]));
}
__device__ __forceinline__ void ldm4(uint32_t* d, uint32_t saddr) {
    asm volatile("ldmatrix.sync.aligned.m8n8.x4.shared.b16 {%0,%1,%2,%3}, [%4];"
                 : "=r"(d[0]), "=r"(d[1]), "=r"(d[2]), "=r"(d[3]) : "r"(saddr));
}
__device__ __forceinline__ uint32_t ldh2(const h16* p) { return *(const uint32_t*)p; }
__device__ __forceinline__ uint32_t pk2(float x, float y) {
    __half2 h = __floats2half2_rn(x, y);
    return *(uint32_t*)&h;
}

#define TS 72
#define T_BUF (128*TS)
#define SMEM_GEMM (4*T_BUF*2)   // 73728 B (2-stage A+B)

// 128x64-half tile, 128 threads
__device__ __forceinline__ void load_t(uint32_t ts, const h16* __restrict__ G, int ld, int tid) {
    #pragma unroll
    for (int i = 0; i < 8; i++) {
        int idx = tid + i*128;
        int m = idx >> 3, ch = idx & 7;
        cpa16(ts + (uint32_t)(m*TS + ch*8)*2, G + (size_t)m*ld + ch*8);
    }
}

// warp tile 64x64 via ldmatrix: 4 m-frags x 8 n-groups
__device__ __forceinline__ void mma_tile64(uint32_t As_u, uint32_t Bs_u,
                                           float acc[4][8][4], int wm, int wn, int lane) {
    const int mat   = lane >> 3;
    const int arow  = (lane & 7) + 8*(mat & 1);
    const int akoff = 8*(mat >> 1);
    const int bg    = (mat >> 1);
    const int bkoff = 8*(mat & 1);
    const int brow  = lane & 7;
    #pragma unroll
    for (int ks = 0; ks < 4; ks++) {
        const int k0 = ks*16;
        uint32_t a[4][4], b[4][4];
        #pragma unroll
        for (int f = 0; f < 4; f++) {
            const int bm = wm*64 + f*16;
            ldm4(a[f], As_u + (uint32_t)((bm + arow)*TS + k0 + akoff)*2);
        }
        #pragma unroll
        for (int gp = 0; gp < 4; gp++) {
            const int bn = wn*64 + (gp*2 + bg)*8;
            ldm4(b[gp], Bs_u + (uint32_t)((bn + brow)*TS + k0 + bkoff)*2);
        }
        #pragma unroll
        for (int f = 0; f < 4; f++)
            #pragma unroll
            for (int g = 0; g < 8; g++) mma16(acc[f][g], a[f], &b[g>>1][(g&1)*2]);
    }
}

// =============================================================================
// P0: fused prep — cvt q/k/v, transpose W + rp tables, cvt Wfc.  One launch.
// grid: [0,12288) cvt3 | [12288,13056) wt(+rp) | [13056,14080) cvtw
// =============================================================================
__global__ __launch_bounds__(256) void prep_all(
    const float* __restrict__ q, const float* __restrict__ k, const float* __restrict__ v,
    const float* __restrict__ wq, const float* __restrict__ wk, const float* __restrict__ wv,
    const float* __restrict__ rpv, const float* __restrict__ rpk,
    const float* __restrict__ wfc)
{
    __shared__ float tile[64*65];
    const int bid = blockIdx.x, tid = threadIdx.x;

    if (bid < 12288) {                       // cvt3
        int mode = bid / 4096;
        int i = (bid % 4096) * 256 + tid;
        const float* in = (mode == 0) ? q : ((mode == 1) ? k : v);
        h16* dst = g_x + (size_t)mode*NM*NHID;
        float4 val = ((const float4*)in)[i];
        __half2 h0 = __floats2half2_rn(val.x, val.y);
        __half2 h1 = __floats2half2_rn(val.z, val.w);
        uint2 u; u.x = *(uint32_t*)&h0; u.y = *(uint32_t*)&h1;
        ((uint2*)dst)[i] = u;
        return;
    }
    if (bid < 13056) {                       // wt (+rp on two blocks)
        int idx = bid - 12288;
        const int hb = idx & 15, n = (idx >> 4) & 15, op = idx >> 8;
        const float* W = (op==0 ? wq : (op==1 ? wk : wv)) + ((size_t)n*NHID + hb*64)*NHD;
        for (int e = tid; e < 64*64; e += 256) {
            int h = e >> 6, d = e & 63;
            tile[h*65 + d] = W[(size_t)h*NHD + d];
        }
        __syncthreads();
        size_t ob = ((size_t)(op*NHEAD + n)*NHD)*NHID + hb*64;
        for (int e = tid; e < 64*64; e += 256) {
            int d = e >> 6, h = e & 63;
            g_wt[ob + (size_t)d*NHID + h] = __float2half(tile[h*65 + d]);
        }
        if (op == 0 && n == 0 && hb == 0) {
            for (int e = tid; e < NHD*NTABP; e += 256) {
                int d = e >> 7, t = e & 127;
                float vv = (t < NTAB) ? rpv[(size_t)t*NHD + d] : 0.f;
                g_rpvt[(size_t)d*NTABP + t] = __float2half(vv);
            }
        }
        if (op == 0 && n == 0 && hb == 1) {
            for (int e = tid; e < NTABP*NHD; e += 256) {
                int t = e >> 6, d = e & 63;
                float vv = (t < NTAB) ? rpk[(size_t)t*NHD + d] : 0.f;
                g_rpkp[e] = __float2half(vv);
            }
        }
        return;
    }
    {                                        // cvtw
        int i = (bid - 13056) * 256 + tid;
        float4 vv = ((const float4*)wfc)[i];
        __half2 h0 = __floats2half2_rn(vv.x, vv.y);
        __half2 h1 = __floats2half2_rn(vv.z, vv.w);
        uint2 u; u.x = *(uint32_t*)&h0; u.y = *(uint32_t*)&h1;
        ((uint2*)g_wfc)[i] = u;
    }
}

// =============================================================================
// K1: QKV projection, 128x128 tiles, 4 warps x 64x64.  grid (32, 8, 3), 128 thr.
// q output is pre-scaled by 0.125.
// =============================================================================
__global__ __launch_bounds__(128) void proj_mma(const float* __restrict__ bq_,
                                                const float* __restrict__ bk_,
                                                const float* __restrict__ bv_)
{
    extern __shared__ char smc[];
    const uint32_t As_u = s2u(smc);
    const uint32_t Bs_u = As_u + 2*T_BUF*2;
    const int tid = threadIdx.x, lane = tid & 31, wid = tid >> 5;
    const int wm = wid & 1, wn = wid >> 1;
    const int m0 = blockIdx.x * 128, ny = blockIdx.y, op = blockIdx.z;

    const h16* A0 = g_x + (size_t)op*NM*NHID + (size_t)m0*NHID;
    const h16* B0 = g_wt + (size_t)(op*NHEAD + ny*2)*NHD*NHID;

    float acc[4][8][4];
    #pragma unroll
    for (int f = 0; f < 4; f++)
        #pragma unroll
        for (int g = 0; g < 8; g++)
            #pragma unroll
            for (int e = 0; e < 4; e++) acc[f][g][e] = 0.f;

    load_t(As_u, A0, NHID, tid);
    load_t(Bs_u, B0, NHID, tid);
    cp_commit();
    for (int kt = 0; kt < 16; kt++) {
        if (kt + 1 < 16) {
            int nb = (kt+1) & 1;
            load_t(As_u + nb*T_BUF*2, A0 + (kt+1)*64, NHID, tid);
            load_t(Bs_u + nb*T_BUF*2, B0 + (kt+1)*64, NHID, tid);
            cp_commit();
            cp_wait<1>();
        } else cp_wait<0>();
        __syncthreads();
        mma_tile64(As_u + (kt&1)*T_BUF*2, Bs_u + (kt&1)*T_BUF*2, acc, wm, wn, lane);
        __syncthreads();
    }

    const int b = m0 >> 10, s0 = m0 & 1023;
    const int r = lane >> 2, cq = lane & 3;
    const float* bias = (op == 0) ? bq_ : ((op == 1) ? bk_ : bv_);

    if (op < 2) {
        h16* outb = op ? g_k : g_q;
        const float sc = (op == 0) ? 0.125f : 1.f;
        #pragma unroll
        for (int f = 0; f < 4; f++) {
            int ml = wm*64 + f*16 + r;
            #pragma unroll
            for (int g = 0; g < 8; g++) {
                int dp = wn*64 + g*8 + 2*cq;
                int nh = ny*2 + (dp >> 6), d = dp & 63;
                float b0 = bias[nh*NHD + d], b1 = bias[nh*NHD + d + 1];
                h16* out = outb + ((size_t)(b*NHEAD + nh)*NS + s0)*NHD;
                *(__half2*)&out[(size_t)ml*NHD + d] =
                    __floats2half2_rn((acc[f][g][0]+b0)*sc, (acc[f][g][1]+b1)*sc);
                *(__half2*)&out[(size_t)(ml+8)*NHD + d] =
                    __floats2half2_rn((acc[f][g][2]+b0)*sc, (acc[f][g][3]+b1)*sc);
            }
        }
    } else {
        h16* stage = (h16*)smc;                   // [128 dp][136]
        #pragma unroll
        for (int f = 0; f < 4; f++) {
            int ml = wm*64 + f*16 + r;
            #pragma unroll
            for (int g = 0; g < 8; g++) {
                int dp = wn*64 + g*8 + 2*cq;
                int nh = ny*2 + (dp >> 6), d = dp & 63;
                float b0 = bias[nh*NHD + d], b1 = bias[nh*NHD + d + 1];
                stage[(dp  )*136 + ml    ] = __float2half(acc[f][g][0] + b0);
                stage[(dp+1)*136 + ml    ] = __float2half(acc[f][g][1] + b1);
                stage[(dp  )*136 + ml + 8] = __float2half(acc[f][g][2] + b0);
                stage[(dp+1)*136 + ml + 8] = __float2half(acc[f][g][3] + b1);
            }
        }
        __syncthreads();
        const int dp = tid;
        const int nh = ny*2 + (dp >> 6), d = dp & 63;
        h16* dst = g_vt + ((size_t)(b*NHEAD + nh)*NHD + d)*NS + s0;
        const uint4* src = (const uint4*)(stage + dp*136);
        #pragma unroll
        for (int j = 0; j < 16; j++) ((uint4*)dst)[j] = src[j];
    }
}

// =============================================================================
// K3: fused flash attention, split K/V prefetch (K hidden behind exp+PV).
// smem: ks[64][72]h @0 | vs @9216 | band @18432 | qbh/wbh @34816 = 52224
// =============================================================================
#define ATTN_SMEM 52224

__global__ __launch_bounds__(128, 4) void attn_fused()
{
    extern __shared__ char smc[];
    h16*  ks   = (h16*)(smc);
    h16*  vs   = (h16*)(smc + 9216);
    h16*  band = (h16*)(smc + 18432);
    h16*  qbh  = (h16*)(smc + 34816);

    const int tid = threadIdx.x, lane = tid & 31, w = tid >> 5;
    const int i0 = blockIdx.x * 64, bn = blockIdx.y;
    const int r = lane >> 2, cq = lane & 3;
    const int cq2 = cq*2;
    const int wb16 = w*16;
    const int lr0 = wb16 + r;
    const int ia0 = i0 + lr0;

    const int mat   = lane >> 3;
    const int arow  = (lane & 7) + 8*(mat & 1);
    const int akoff = 8*(mat >> 1);
    const int bg    = (mat >> 1);
    const int bkoff = 8*(mat & 1);
    const int brow  = lane & 7;

    const uint32_t ks_u = s2u(ks), vs_u = s2u(vs), bd_u = s2u(band);

    const h16* qg = g_q + ((size_t)bn*NS + i0)*NHD;
    for (int e = tid; e < 64*8; e += 128) {
        int row = e >> 3, ch = e & 7;
        cpa16(bd_u + (uint32_t)(row*72 + ch*8)*2, qg + (size_t)row*NHD + ch*8);
    }
    for (int e = tid; e < 128*8; e += 128) {
        int row = e >> 3, ch = e & 7;
        cpa16(ks_u + (uint32_t)(row*72 + ch*8)*2, g_rpkp + (size_t)row*NHD + ch*8);
    }
    cp_commit();
    cp_wait<0>();
    __syncthreads();

    uint32_t qf[4][4];
    #pragma unroll
    for (int kk = 0; kk < 4; kk++)
        ldm4(qf[kk], bd_u + (uint32_t)((wb16 + arow)*72 + kk*16 + akoff)*2);

    {
        float qacc[16][4];
        #pragma unroll
        for (int g = 0; g < 16; g++)
            #pragma unroll
            for (int e = 0; e < 4; e++) qacc[g][e] = 0.f;
        #pragma unroll
        for (int kk = 0; kk < 4; kk++) {
            const int k0 = kk*16;
            #pragma unroll
            for (int gp = 0; gp < 8; gp++) {
                uint32_t b[4];
                ldm4(b, ks_u + (uint32_t)(((gp*2 + bg)*8 + brow)*72 + k0 + bkoff)*2);
                mma16(qacc[gp*2    ], qf[kk], &b[0]);
                mma16(qacc[gp*2 + 1], qf[kk], &b[2]);
            }
        }
        __syncthreads();
        #pragma unroll
        for (int g = 0; g < 16; g++) {
            const int t = g*8 + cq2;
            *(uint32_t*)&qbh[lr0*136 + t]     = pk2(qacc[g][0], qacc[g][1]);
            *(uint32_t*)&qbh[(lr0+8)*136 + t] = pk2(qacc[g][2], qacc[g][3]);
        }
    }
    for (int e = tid; e < 64*128/8; e += 128)
        ((uint4*)band)[e] = make_uint4(0,0,0,0);
    __syncthreads();

    const float el0 = __expf(__half2float(qbh[lr0*136 +   0]));
    const float er0 = __expf(__half2float(qbh[lr0*136 + 126]));
    const float el1 = __expf(__half2float(qbh[(lr0+8)*136 +   0]));
    const float er1 = __expf(__half2float(qbh[(lr0+8)*136 + 126]));

    const h16* kg = g_k + (size_t)bn*NS*NHD;
    const h16* vg = g_vt + (size_t)bn*NHD*NS;

    auto ldK = [&](int jt) {
        for (int e = tid; e < 64*8; e += 128) {
            int row = e >> 3, ch = e & 7;
            cpa16(ks_u + (uint32_t)(row*72 + ch*8)*2,
                  kg + (size_t)(jt*64+row)*NHD + ch*8);
        }
    };
    auto ldV = [&](int jt) {
        for (int e = tid; e < 64*8; e += 128) {
            int d = e >> 3, ch = e & 7;
            cpa16(vs_u + (uint32_t)(d*72 + ch*8)*2,
                  vg + (size_t)d*NS + jt*64 + ch*8);
        }
    };
    ldK(0); ldV(0); cp_commit();

    float o[8][4];
    #pragma unroll
    for (int g = 0; g < 8; g++)
        #pragma unroll
        for (int e = 0; e < 4; e++) o[g][e] = 0.f;
    float l0 = 0.f, l1 = 0.f;
    float rs0 = 0.f, rs1 = 0.f;

    for (int jt = 0; jt < 16; jt++) {
        cp_wait<0>();
        __syncthreads();                      // K(jt), V(jt) visible to all

        // ---- QK^T (64 x 64): q regs, K via ldmatrix ----
        float s[8][4];
        #pragma unroll
        for (int g = 0; g < 8; g++)
            #pragma unroll
            for (int e = 0; e < 4; e++) s[g][e] = 0.f;
        #pragma unroll
        for (int kk = 0; kk < 4; kk++) {
            const int k0 = kk*16;
            #pragma unroll
            for (int gp = 0; gp < 4; gp++) {
                uint32_t b[4];
                ldm4(b, ks_u + (uint32_t)(((gp*2 + bg)*8 + brow)*72 + k0 + bkoff)*2);
                mma16(s[gp*2    ], qf[kk], &b[0]);
                mma16(s[gp*2 + 1], qf[kk], &b[2]);
            }
        }
        __syncthreads();                      // K buffer free -> prefetch K(jt+1)
        if (jt + 1 < 16) { ldK(jt+1); cp_commit(); }

        // ---- softmax numerators ----
        const int d64 = jt*64 - i0;
        if (d64 <= -128) {
            #pragma unroll
            for (int g = 0; g < 8; g++) {
                float p0 = __expf(s[g][0])*el0;
                float p1 = __expf(s[g][1])*el0;
                float p2 = __expf(s[g][2])*el1;
                float p3 = __expf(s[g][3])*el1;
                l0 += p0 + p1; l1 += p2 + p3;
                s[g][0]=p0; s[g][1]=p1; s[g][2]=p2; s[g][3]=p3;
            }
        } else if (d64 >= 128) {
            #pragma unroll
            for (int g = 0; g < 8; g++) {
                float p0 = __expf(s[g][0])*er0;
                float p1 = __expf(s[g][1])*er0;
                float p2 = __expf(s[g][2])*er1;
                float p3 = __expf(s[g][3])*er1;
                l0 += p0 + p1; l1 += p2 + p3;
                rs0 += p0 + p1; rs1 += p2 + p3;
                s[g][0]=p0; s[g][1]=p1; s[g][2]=p2; s[g][3]=p3;
            }
        } else {
            #pragma unroll
            for (int g = 0; g < 8; g++) {
                const int j0 = jt*64 + g*8 + cq2;
                const int t0 = j0 - ia0 + 63;
                const int t8 = t0 - 8;
                int c0 = t0 < 0 ? 0 : (t0 > 126 ? 126 : t0);
                int c1 = t0+1 < 0 ? 0 : (t0+1 > 126 ? 126 : t0+1);
                int c2 = t8 < 0 ? 0 : (t8 > 126 ? 126 : t8);
                int c3 = t8+1 < 0 ? 0 : (t8+1 > 126 ? 126 : t8+1);
                float p0 = __expf(s[g][0] + __half2float(qbh[lr0*136 + c0]));
                float p1 = __expf(s[g][1] + __half2float(qbh[lr0*136 + c1]));
                float p2 = __expf(s[g][2] + __half2float(qbh[(lr0+8)*136 + c2]));
                float p3 = __expf(s[g][3] + __half2float(qbh[(lr0+8)*136 + c3]));
                band[lr0*128 + c0]     = __float2half(p0);
                band[lr0*128 + c1]     = __float2half(p1);
                band[(lr0+8)*128 + c2] = __float2half(p2);
                band[(lr0+8)*128 + c3] = __float2half(p3);
                l0 += p0 + p1; l1 += p2 + p3;
                if (t0   >= 126) rs0 += p0;
                if (t0+1 >= 126) rs0 += p1;
                if (t8   >= 126) rs1 += p2;
                if (t8+1 >= 126) rs1 += p3;
                s[g][0]=p0; s[g][1]=p1; s[g][2]=p2; s[g][3]=p3;
            }
        }

        // ---- PV from register fragments + ldmatrix V ----
        #pragma unroll
        for (int kk = 0; kk < 4; kk++) {
            const int k0 = kk*16;
            uint32_t a[4];
            a[0] = pk2(s[2*kk  ][0], s[2*kk  ][1]);
            a[1] = pk2(s[2*kk  ][2], s[2*kk  ][3]);
            a[2] = pk2(s[2*kk+1][0], s[2*kk+1][1]);
            a[3] = pk2(s[2*kk+1][2], s[2*kk+1][3]);
            #pragma unroll
            for (int gp = 0; gp < 4; gp++) {
                uint32_t b[4];
                ldm4(b, vs_u + (uint32_t)(((gp*2 + bg)*8 + brow)*72 + k0 + bkoff)*2);
                mma16(o[gp*2    ], a, &b[0]);
                mma16(o[gp*2 + 1], a, &b[2]);
            }
        }
        __syncthreads();                      // V buffer free -> prefetch V(jt+1)
        if (jt + 1 < 16) { ldV(jt+1); cp_commit(); }
    }

    // ---- epilogue ----
    __syncwarp();
    float bs0 = 0.f, bs1 = 0.f;
    for (int t = 1 + cq; t <= 125; t += 4) {
        bs0 += __half2float(band[lr0*128 + t]);
        bs1 += __half2float(band[(lr0+8)*128 + t]);
    }
    #pragma unroll
    for (int off = 1; off <= 2; off <<= 1) {
        l0  += __shfl_xor_sync(0xffffffffu, l0,  off);
        l1  += __shfl_xor_sync(0xffffffffu, l1,  off);
        rs0 += __shfl_xor_sync(0xffffffffu, rs0, off);
        rs1 += __shfl_xor_sync(0xffffffffu, rs1, off);
        bs0 += __shfl_xor_sync(0xffffffffu, bs0, off);
        bs1 += __shfl_xor_sync(0xffffffffu, bs1, off);
    }
    const float ls0 = l0 - rs0 - bs0;
    const float ls1 = l1 - rs1 - bs1;
    const float inv0 = 1.f / l0, inv1 = 1.f / l1;
    #pragma unroll
    for (int g = 0; g < 8; g++) {
        o[g][0] *= inv0; o[g][1] *= inv0; o[g][2] *= inv1; o[g][3] *= inv1;
    }
    __syncthreads();

    h16* rvs = (h16*)smc;
    h16* wbh = qbh;
    for (int e = tid; e < 64*16; e += 128) {
        int d = e >> 4, ch = e & 15;
        cpa16(s2u(rvs + d*136 + ch*8), g_rpvt + (size_t)d*NTABP + ch*8);
    }
    cp_commit();
    for (int t = cq; t < 128; t += 4) {
        float v0 = 0.f, v1 = 0.f;
        if (t == 0)        { v0 = ls0*inv0; v1 = ls1*inv1; }
        else if (t == 126) { v0 = rs0*inv0; v1 = rs1*inv1; }
        else if (t < 126) {
            int j0 = ia0 + t - 63;
            int j1 = j0 + 8;
            if (j0 >= 0 && j0 < NS) v0 = __half2float(band[lr0*128 + t]) * inv0;
            if (j1 >= 0 && j1 < NS) v1 = __half2float(band[(lr0+8)*128 + t]) * inv1;
        }
        wbh[lr0*136 + t]     = __float2half(v0);
        wbh[(lr0+8)*136 + t] = __float2half(v1);
    }
    cp_wait<0>();
    __syncthreads();

    #pragma unroll
    for (int kk = 0; kk < 8; kk++) {
        const int k0 = kk*16;
        uint32_t a[4];
        a[0] = ldh2(&wbh[(lr0  )*136 + k0 + cq2    ]);
        a[1] = ldh2(&wbh[(lr0+8)*136 + k0 + cq2    ]);
        a[2] = ldh2(&wbh[(lr0  )*136 + k0 + cq2 + 8]);
        a[3] = ldh2(&wbh[(lr0+8)*136 + k0 + cq2 + 8]);
        #pragma unroll
        for (int g = 0; g < 8; g++) {
            uint32_t b[2];
            b[0] = ldh2(&rvs[(g*8+r)*136 + k0 + cq2    ]);
            b[1] = ldh2(&rvs[(g*8+r)*136 + k0 + cq2 + 8]);
            mma16(o[g], a, b);
        }
    }

    const int b = bn >> 4, n = bn & 15;
    #pragma unroll
    for (int g = 0; g < 8; g++) {
        const int d = g*8 + cq2;
        h16* p0 = g_ao + ((size_t)(b*NS + i0 + lr0))*NHID + n*NHD + d;
        h16* p1 = g_ao + ((size_t)(b*NS + i0 + lr0 + 8))*NHID + n*NHD + d;
        *(__half2*)p0 = __floats2half2_rn(o[g][0], o[g][1]);
        *(__half2*)p1 = __floats2half2_rn(o[g][2], o[g][3]);
    }
}

// =============================================================================
// K5: final FC, 128x128 tiles, 4 warps x 64x64.  grid (32, 8), 128 thr.
// =============================================================================
__global__ __launch_bounds__(128) void fc_mma(const float* __restrict__ bfc,
                                              float* __restrict__ out)
{
    extern __shared__ char smc[];
    const uint32_t As_u = s2u(smc);
    const uint32_t Bs_u = As_u + 2*T_BUF*2;
    const int tid = threadIdx.x, lane = tid & 31, wid = tid >> 5;
    const int wm = wid & 1, wn = wid >> 1;
    const int m0 = blockIdx.x * 128, o0 = blockIdx.y * 128;

    const h16* A0 = g_ao + (size_t)m0*NHID;
    const h16* B0 = g_wfc + (size_t)o0*NHID;

    float acc[4][8][4];
    #pragma unroll
    for (int f = 0; f < 4; f++)
        #pragma unroll
        for (int g = 0; g < 8; g++)
            #pragma unroll
            for (int e = 0; e < 4; e++) acc[f][g][e] = 0.f;

    load_t(As_u, A0, NHID, tid);
    load_t(Bs_u, B0, NHID, tid);
    cp_commit();
    for (int kt = 0; kt < 16; kt++) {
        if (kt + 1 < 16) {
            int nb = (kt+1) & 1;
            load_t(As_u + nb*T_BUF*2, A0 + (kt+1)*64, NHID, tid);
            load_t(Bs_u + nb*T_BUF*2, B0 + (kt+1)*64, NHID, tid);
            cp_commit();
            cp_wait<1>();
        } else cp_wait<0>();
        __syncthreads();
        mma_tile64(As_u + (kt&1)*T_BUF*2, Bs_u + (kt&1)*T_BUF*2, acc, wm, wn, lane);
        __syncthreads();
    }

    const int r = lane >> 2, cq = lane & 3;
    #pragma unroll
    for (int f = 0; f < 4; f++) {
        int m = m0 + wm*64 + f*16 + r;
        #pragma unroll
        for (int g = 0; g < 8; g++) {
            int o = o0 + wn*64 + g*8 + 2*cq;
            float b0 = bfc[o], b1 = bfc[o+1];
            *(float2*)&out[(size_t)m*NHID + o]     = make_float2(acc[f][g][0]+b0, acc[f][g][1]+b1);
            *(float2*)&out[(size_t)(m+8)*NHID + o] = make_float2(acc[f][g][2]+b0, acc[f][g][3]+b1);
        }
    }
}

// =============================================================================
extern "C" void kernel_launch(void* const* d_in, const int* in_sizes, int n_in,
                              void* d_out, int out_size)
{
    (void)in_sizes; (void)n_in; (void)out_size;
    const float* query = (const float*)d_in[0];
    const float* key   = (const float*)d_in[1];
    const float* value = (const float*)d_in[2];
    const float* Wq    = (const float*)d_in[3];
    const float* Wk    = (const float*)d_in[4];
    const float* Wv    = (const float*)d_in[5];
    const float* bq    = (const float*)d_in[6];
    const float* bk    = (const float*)d_in[7];
    const float* bv    = (const float*)d_in[8];
    const float* rpk   = (const float*)d_in[9];
    const float* rpv   = (const float*)d_in[10];
    const float* Wfc   = (const float*)d_in[11];
    const float* bfc   = (const float*)d_in[12];
    float* out = (float*)d_out;

    cudaFuncSetAttribute(proj_mma,   cudaFuncAttributeMaxDynamicSharedMemorySize, SMEM_GEMM);
    cudaFuncSetAttribute(fc_mma,     cudaFuncAttributeMaxDynamicSharedMemorySize, SMEM_GEMM);
    cudaFuncSetAttribute(attn_fused, cudaFuncAttributeMaxDynamicSharedMemorySize, ATTN_SMEM);

    prep_all<<<14080, 256>>>(query, key, value, Wq, Wk, Wv, rpv, rpk, Wfc);  // 1
    proj_mma<<<dim3(32, 8, 3), 128, SMEM_GEMM>>>(bq, bk, bv);                // 2
    attn_fused<<<dim3(16, 64), 128, ATTN_SMEM>>>();                          // 3
    fc_mma<<<dim3(32, 8), 128, SMEM_GEMM>>>(bfc, out);                       // 4 <- profiled
}